// round 14
// baseline (speedup 1.0000x reference)
#include <cuda_runtime.h>
#include <cuda_bf16.h>
#include <math.h>
#include <stdint.h>

constexpr int Bn=4, Tn=1024, DMn=1024, Hn=16, DKn=64;
constexpr int BT=Bn*Tn, PLANE=BT*DMn, NBH=Bn*Hn;
constexpr size_t SSZ=(size_t)NBH*Tn*Tn;
constexpr int DT_BH=128*Tn, VT_BH=64*Tn;
constexpr int DSMEM=81920;             // gemm128: 2 stages x (4 planes x 128 x 80B)
constexpr int PSZ=128*80, STG=4*PSZ;
// scores smem: Stile 32x1032 f32 (132096) + Q hi/lo (2x4608) + K 2 bufs x 2 planes x 128r x 144B
constexpr int SC_STILE=0, SC_Q=132096, SC_K=141312;
constexpr int QPL=4608, KPLC=18432;    // Q plane (32r), K chunk plane (128r), stride 144B
constexpr int KBUF=2*KPLC;             // one K buffer (hi+lo) = 36864
constexpr int SC_SMEM=SC_K+2*KBUF;     // 215040

// ---- scratch ----
__device__ __nv_bfloat16 g_xHi[PLANE], g_xLo[PLANE];
__device__ __nv_bfloat16 g_WHi[6][DMn*DMn], g_WLo[6][DMn*DMn];   // W^T split [n][k]
__device__ __nv_bfloat16 g_QHi[PLANE], g_QLo[PLANE], g_KHi[PLANE], g_KLo[PLANE];
__device__ __nv_bfloat16 g_AHi[SSZ];                             // adjacency, single bf16
__device__ float        g_DtF [(size_t)NBH*DT_BH];               // final-step fp32 (readout)
__device__ __nv_bfloat16 g_DtHi[2][(size_t)NBH*DT_BH], g_DtLo[2][(size_t)NBH*DT_BH];
__device__ float g_VT[(size_t)NBH*VT_BH], g_gvT[(size_t)NBH*VT_BH], g_gateT[(size_t)NBH*VT_BH];
__device__ __nv_bfloat16 g_gvHi[PLANE], g_gvLo[PLANE];
__device__ float g_gateS[(size_t)NBH*Tn*DKn];

// ---- helpers ----
__device__ __forceinline__ uint32_t smem_u32(const void* p){
    uint32_t a; asm("{ .reg .u64 t; cvta.to.shared.u64 t, %1; cvt.u32.u64 %0, t; }":"=r"(a):"l"(p)); return a;
}
__device__ __forceinline__ void cp16(uint32_t s, const void* g){
    asm volatile("cp.async.cg.shared.global [%0], [%1], 16;"::"r"(s),"l"(__cvta_generic_to_global(g)):"memory");
}
#define CP_COMMIT() asm volatile("cp.async.commit_group;":::"memory")
#define CP_WAIT0()  asm volatile("cp.async.wait_group 0;":::"memory")
#define LDM_X4(r,a) asm volatile("ldmatrix.sync.aligned.m8n8.x4.shared.b16 {%0,%1,%2,%3}, [%4];" \
    : "=r"((r)[0]),"=r"((r)[1]),"=r"((r)[2]),"=r"((r)[3]) : "r"(a))
__device__ __forceinline__ void mma16816(float* c, const uint32_t* a, uint32_t b0, uint32_t b1){
    asm volatile("mma.sync.aligned.m16n8k16.row.col.f32.bf16.bf16.f32 "
        "{%0,%1,%2,%3}, {%4,%5,%6,%7}, {%8,%9}, {%0,%1,%2,%3};"
        : "+f"(c[0]),"+f"(c[1]),"+f"(c[2]),"+f"(c[3])
        : "r"(a[0]),"r"(a[1]),"r"(a[2]),"r"(a[3]),"r"(b0),"r"(b1));
}

// ---- gemm128: 128x128 tile, 256 thr, 2-stage cp.async K=32, ONE barrier/chunk (R11 proven) ----
__device__ __forceinline__ void load_plane(uint32_t s, const __nv_bfloat16* g, int ld, int tid){
#pragma unroll
    for(int i=0;i<2;i++){
        int idx=tid+(i<<8), row=idx>>2, seg=idx&3;
        cp16(s+row*80+seg*16, g+(size_t)row*ld+seg*8);
    }
}
template<bool BLO>
__device__ __forceinline__ void load_chunk(uint32_t sb,
    const __nv_bfloat16* aHi,const __nv_bfloat16* aLo,int lda,
    const __nv_bfloat16* bHi,const __nv_bfloat16* bLo,int ldb,int c,int tid){
    size_t ko=(size_t)c*32;
    load_plane(sb,        aHi+ko, lda, tid);
    load_plane(sb+PSZ,    aLo+ko, lda, tid);
    load_plane(sb+2*PSZ,  bHi+ko, ldb, tid);
    if(BLO) load_plane(sb+3*PSZ,  bLo+ko, ldb, tid);
}
template<bool BLO>
__device__ __forceinline__ void compute_stage(uint32_t sb,int wm,int wn,int lane,float acc[2][8][4]){
#pragma unroll
    for(int kk=0;kk<32;kk+=16){
        uint32_t a_hi[2][4], a_lo[2][4];
#pragma unroll
        for(int mi=0;mi<2;mi++){
            uint32_t ad=sb+(uint32_t)((wm*32+mi*16+(lane&15))*80+(kk+((lane>>4)<<3))*2);
            LDM_X4(a_hi[mi],ad); LDM_X4(a_lo[mi],ad+PSZ);
        }
#pragma unroll
        for(int np=0;np<4;np++){
            uint32_t bd=sb+2*PSZ+(uint32_t)((wn*64+np*16+(lane&7)+((lane>>4)<<3))*80+(kk+((lane>>3)&1)*8)*2);
            uint32_t bh[4], bl[4];
            LDM_X4(bh,bd);
            if(BLO){ LDM_X4(bl,bd+PSZ); }
#pragma unroll
            for(int mi=0;mi<2;mi++)
#pragma unroll
                for(int j=0;j<2;j++){
                    float* c=acc[mi][np*2+j];
                    mma16816(c,a_hi[mi],bh[2*j],bh[2*j+1]);
                    if(BLO) mma16816(c,a_hi[mi],bl[2*j],bl[2*j+1]);
                    mma16816(c,a_lo[mi],bh[2*j],bh[2*j+1]);
                }
        }
    }
}
template<bool BLO>
__device__ __forceinline__ void gemm128(uint32_t dsm_u32,
    const __nv_bfloat16* aHi,const __nv_bfloat16* aLo,int lda,
    const __nv_bfloat16* bHi,const __nv_bfloat16* bLo,int ldb,
    int nchunks, float acc[2][8][4]){
    int tid=threadIdx.x, lane=tid&31, wid=tid>>5, wm=wid>>1, wn=wid&1;
    load_chunk<BLO>(dsm_u32, aHi,aLo,lda, bHi,bLo,ldb, 0, tid); CP_COMMIT();
    for(int c=0;c<nchunks;c++){
        CP_WAIT0();
        __syncthreads();
        if(c+1<nchunks){
            load_chunk<BLO>(dsm_u32+((c+1)&1)*STG, aHi,aLo,lda, bHi,bLo,ldb, c+1, tid);
            CP_COMMIT();
        }
        compute_stage<BLO>(dsm_u32+(c&1)*STG, wm, wn, lane, acc);
    }
    __syncthreads();
}

// ---- fused projections: z selects weight + output mode ----
__global__ void __launch_bounds__(256,2)
proj_all_kernel(const __nv_bfloat16* __restrict__ aHi,const __nv_bfloat16* __restrict__ aLo,
                int zbase, float* __restrict__ outF){
    extern __shared__ char dsm[];
    int z=blockIdx.z+zbase;
    const __nv_bfloat16* wHi=&g_WHi[z][0];
    const __nv_bfloat16* wLo=&g_WLo[z][0];
    float acc[2][8][4]={};
    int m0=blockIdx.y*128, n0=blockIdx.x*128;
    gemm128<true>(smem_u32(dsm), aHi+(size_t)m0*1024, aLo+(size_t)m0*1024,1024,
            wHi+(size_t)n0*1024, wLo+(size_t)n0*1024,1024, 32, acc);
    int tid=threadIdx.x, lane=tid&31, wid=tid>>5, wm=wid>>1, wn=wid&1, g=lane>>2, tg=lane&3;
    int mode = (z<2)?1 : (z<4)?2 : (z==4)?3 : 0;
    int rowoff = (z==3)?64:0;
    __nv_bfloat16 *oHi=nullptr,*oLo=nullptr; float* oF=nullptr;
    if(z==0){ oHi=g_QHi; oLo=g_QLo; }
    else if(z==1){ oHi=g_KHi; oLo=g_KLo; }
    else if(z<4){ oHi=&g_DtHi[0][0]; oLo=&g_DtLo[0][0]; }
    else if(z==4){ oF=g_VT; }
    else { oF=outF; }
    if(mode<=1){
#pragma unroll
        for(int mi=0;mi<2;mi++)
#pragma unroll
        for(int ni=0;ni<8;ni++){
            float* a4=acc[mi][ni];
            int cl=n0+wn*64+ni*8+tg*2;
#pragma unroll
            for(int p=0;p<2;p++){
                int row=m0+wm*32+mi*16+g+p*8;
                float v0=a4[2*p], v1=a4[2*p+1];
                if(mode==0){
                    *(float2*)&oF[(size_t)row*1024+cl]=make_float2(v0,v1);
                } else {
                    size_t dst=(size_t)row*1024+cl;
                    __nv_bfloat16 h0=__float2bfloat16(v0), h1=__float2bfloat16(v1);
                    *(__nv_bfloat162*)&oHi[dst]=__nv_bfloat162(h0,h1);
                    *(__nv_bfloat162*)&oLo[dst]=__nv_bfloat162(
                        __float2bfloat16(v0-__bfloat162float(h0)),
                        __float2bfloat16(v1-__bfloat162float(h1)));
                }
            }
        }
    } else {
        // transposed outputs: stage through smem for coalesced stores along t
        float* T=(float*)dsm;   // [128 cl][132 row-stride]
#pragma unroll
        for(int mi=0;mi<2;mi++)
#pragma unroll
        for(int ni=0;ni<8;ni++){
            float* a4=acc[mi][ni];
            int cl=wn*64+ni*8+tg*2;
#pragma unroll
            for(int p=0;p<2;p++){
                int row=wm*32+mi*16+g+p*8;
                T[cl*132+row]    =a4[2*p];
                T[(cl+1)*132+row]=a4[2*p+1];
            }
        }
        __syncthreads();
        int j=tid>>1, half=tid&1;
        int dm=n0+j, h=dm>>6, d=dm&63, bq=m0>>10, bh=bq*16+h;
        int t0=(m0&1023)+half*64;
        const float* src=&T[j*132+half*64];
        if(mode==2){
            size_t o0=(size_t)bh*DT_BH+(size_t)(rowoff+d)*1024+t0;
#pragma unroll
            for(int k8=0;k8<8;k8++){
                __align__(16) __nv_bfloat16 hb[8], lb[8];
#pragma unroll
                for(int k=0;k<8;k++){
                    float v=src[k8*8+k];
                    __nv_bfloat16 hh=__float2bfloat16(v);
                    hb[k]=hh; lb[k]=__float2bfloat16(v-__bfloat162float(hh));
                }
                *(uint4*)&oHi[o0+k8*8]=*(const uint4*)hb;
                *(uint4*)&oLo[o0+k8*8]=*(const uint4*)lb;
            }
        } else {
            size_t o0=(size_t)bh*VT_BH+(size_t)d*1024+t0;
#pragma unroll
            for(int k4=0;k4<16;k4++)
                *(float4*)&oF[o0+k4*4]=*(const float4*)&src[k4*4];
        }
    }
}

// ---- fused scores + softmax; K double-buffered (128-row chunks) ----
__global__ void __launch_bounds__(512,1)
scores_softmax_kernel(){
    extern __shared__ char dsm[];
    float* Stile=(float*)(dsm+SC_STILE);           // [32][1032]
    uint32_t qoff=smem_u32(dsm)+SC_Q, kbase=smem_u32(dsm)+SC_K;
    int tid=threadIdx.x, lane=tid&31, wid=tid>>5;
    int wm=wid>>3, wn=wid&7;                       // 2m x 8n, warp tile 16x16
    int m0=blockIdx.x*32, bh=blockIdx.y, b=bh>>4, h=bh&15;
    size_t qg=(size_t)(b*1024+m0)*1024+h*64;
    size_t kg=(size_t)(b*1024)*1024+h*64;

    // prologue: Q (32 rows hi+lo) + K chunk 0, one group
    {
        int p=tid>>8, i=tid&255, row=i>>3, seg=i&7;
        const __nv_bfloat16* src=(p? g_QLo:g_QHi)+qg+(size_t)row*1024+seg*8;
        cp16(qoff+p*QPL+row*144+seg*16, src);
    }
#pragma unroll
    for(int j=0;j<4;j++){
        int idx=tid+j*512, p=idx>>10, i=idx&1023, row=i>>3, seg=i&7;
        const __nv_bfloat16* src=(p? g_KLo:g_KHi)+kg+(size_t)row*1024+seg*8;
        cp16(kbase+p*KPLC+row*144+seg*16, src);
    }
    CP_COMMIT();

    for(int c=0;c<8;c++){
        CP_WAIT0();
        __syncthreads();
        if(c+1<8){
            uint32_t kb=kbase+((c+1)&1)*KBUF;
#pragma unroll
            for(int j=0;j<4;j++){
                int idx=tid+j*512, p=idx>>10, i=idx&1023, row=i>>3, seg=i&7;
                const __nv_bfloat16* src=(p? g_KLo:g_KHi)+kg+(size_t)((c+1)*128+row)*1024+seg*8;
                cp16(kb+p*KPLC+row*144+seg*16, src);
            }
            CP_COMMIT();
        }
        uint32_t kb=kbase+(c&1)*KBUF;
        float acc[2][4]={};
#pragma unroll
        for(int kk=0;kk<64;kk+=16){
            uint32_t ah[4], al[4];
            uint32_t ad=qoff+(uint32_t)((wm*16+(lane&15))*144+(kk+((lane>>4)<<3))*2);
            LDM_X4(ah,ad); LDM_X4(al,ad+QPL);
            uint32_t bd=kb+(uint32_t)((wn*16+(lane&7)+((lane>>4)<<3))*144+(kk+((lane>>3)&1)*8)*2);
            uint32_t bh4[4], bl4[4];
            LDM_X4(bh4,bd); LDM_X4(bl4,bd+KPLC);
#pragma unroll
            for(int j=0;j<2;j++){
                float* cc=acc[j];
                mma16816(cc,ah,bh4[2*j],bh4[2*j+1]);
                mma16816(cc,ah,bl4[2*j],bl4[2*j+1]);
                mma16816(cc,al,bh4[2*j],bh4[2*j+1]);
            }
        }
        int cb=c*128+wn*16;
        int g=lane>>2, tg=lane&3;
#pragma unroll
        for(int j=0;j<2;j++){
#pragma unroll
            for(int p=0;p<2;p++){
                int r=wm*16+g+p*8, cc=cb+j*8+tg*2;
                Stile[r*1032+cc]  =acc[j][2*p]  *0.125f;
                Stile[r*1032+cc+1]=acc[j][2*p+1]*0.125f;
            }
        }
    }
    __syncthreads();

    for(int rr=0;rr<2;rr++){
        int r=wid*2+rr;
        float* row=&Stile[r*1032];
        float mx=-1e30f;
        for(int c=lane;c<1024;c+=32) mx=fmaxf(mx,row[c]);
#pragma unroll
        for(int o=16;o;o>>=1) mx=fmaxf(mx,__shfl_xor_sync(0xffffffffu,mx,o));
        float s=0.f;
        for(int c=lane;c<1024;c+=32){ float e=expf(row[c]-mx); row[c]=e; s+=e; }
#pragma unroll
        for(int o=16;o;o>>=1) s+=__shfl_xor_sync(0xffffffffu,s,o);
        float inv=1.f/s;
        size_t ob=((size_t)bh<<20)+(size_t)(m0+r)*1024;
        for(int c=lane;c<1024;c+=32)
            g_AHi[ob+c]=__float2bfloat16(row[c]*inv);
    }
}

// ---- propagation: Dt_out=(1-lam)Dt_in + lam*(Dt_in@A^T); din from hi+lo ----
__global__ void __launch_bounds__(256,2)
prop_kernel(const __nv_bfloat16* __restrict__ dHi,const __nv_bfloat16* __restrict__ dLo,
            float* __restrict__ outF,__nv_bfloat16* __restrict__ outHi,__nv_bfloat16* __restrict__ outLo,
            const float* __restrict__ lam_ptr, int ws){
    extern __shared__ char dsm[];
    float acc[2][8][4]={};
    int n0=blockIdx.x*128, bh=blockIdx.y;
    size_t ab=(size_t)bh*DT_BH, bb=((size_t)bh<<20)+(size_t)n0*1024;
    gemm128<false>(smem_u32(dsm), dHi+ab,dLo+ab,1024, g_AHi+bb,nullptr,1024, 32, acc);
    float lam=1.f/(1.f+expf(-lam_ptr[0])), oml=1.f-lam;
    int tid=threadIdx.x, lane=tid&31, wid=tid>>5, wm=wid>>1, wn=wid&1, g=lane>>2, tg=lane&3;
#pragma unroll
    for(int mi=0;mi<2;mi++)
#pragma unroll
    for(int ni=0;ni<8;ni++){
        float* a4=acc[mi][ni];
        int cl=n0+wn*64+ni*8+tg*2;
#pragma unroll
        for(int p=0;p<2;p++){
            int r=wm*32+mi*16+g+p*8;
            size_t off=ab+(size_t)r*1024+cl;
            __nv_bfloat162 h2=*(const __nv_bfloat162*)&dHi[off];
            __nv_bfloat162 l2=*(const __nv_bfloat162*)&dLo[off];
            float din0=__bfloat162float(h2.x)+__bfloat162float(l2.x);
            float din1=__bfloat162float(h2.y)+__bfloat162float(l2.y);
            float v0=oml*din0+lam*a4[2*p], v1=oml*din1+lam*a4[2*p+1];
            if(ws){
                __nv_bfloat16 h0=__float2bfloat16(v0), h1=__float2bfloat16(v1);
                *(__nv_bfloat162*)&outHi[off]=__nv_bfloat162(h0,h1);
                *(__nv_bfloat162*)&outLo[off]=__nv_bfloat162(
                    __float2bfloat16(v0-__bfloat162float(h0)),
                    __float2bfloat16(v1-__bfloat162float(h1)));
            } else {
                *(float2*)&outF[off]=make_float2(v0,v1);
            }
        }
    }
}

// ---- readout: one warp per (bh, d) column ----
__global__ void __launch_bounds__(256)
readout_kernel(const float* __restrict__ DtF,const float* __restrict__ VT,
               float* __restrict__ gateT,float* __restrict__ gvT){
    int bh=blockIdx.y, w=threadIdx.x>>5, lane=threadIdx.x&31;
    int d=blockIdx.x*8+w;
    const float* base=DtF+(size_t)bh*DT_BH;
    const float* vb=VT+(size_t)bh*VT_BH;
    const float* rRe=base+(size_t)d*1024;
    const float* rIm=base+(size_t)(64+d)*1024;
    float sre=0.f,sim=0.f;
    for(int t=lane;t<1024;t+=32){ sre+=rRe[t]; sim+=rIm[t]; }
#pragma unroll
    for(int o=16;o;o>>=1){ sre+=__shfl_xor_sync(0xffffffffu,sre,o); sim+=__shfl_xor_sync(0xffffffffu,sim,o); }
    float mre=sre*(1.f/1024.f), mim=sim*(1.f/1024.f);
    float mn=sqrtf(mre*mre+mim*mim);
    float mx=-1e30f;
    for(int t=lane;t<1024;t+=32){
        float re=rRe[t], im=rIm[t];
        mx=fmaxf(mx,(re*mre+im*mim)/(sqrtf(re*re+im*im)*mn+1e-8f));
    }
#pragma unroll
    for(int o=16;o;o>>=1) mx=fmaxf(mx,__shfl_xor_sync(0xffffffffu,mx,o));
    float ss=0.f;
    for(int t=lane;t<1024;t+=32){
        float re=rRe[t], im=rIm[t];
        ss+=expf((re*mre+im*mim)/(sqrtf(re*re+im*im)*mn+1e-8f)-mx);
    }
#pragma unroll
    for(int o=16;o;o>>=1) ss+=__shfl_xor_sync(0xffffffffu,ss,o);
    float inv=1.f/ss;
    size_t ob=(size_t)bh*VT_BH+(size_t)d*1024;
    for(int t=lane;t<1024;t+=32){
        float re=rRe[t], im=rIm[t];
        float gt=expf((re*mre+im*mim)/(sqrtf(re*re+im*im)*mn+1e-8f)-mx)*inv;
        gateT[ob+t]=gt; gvT[ob+t]=gt*vb[(size_t)d*1024+t];
    }
}

// ---- gather ----
__global__ void gather_kernel(const float* __restrict__ gvT,const float* __restrict__ gateT,
                              float* __restrict__ gate){
    __shared__ float tv[32][33], tg2[32][33];
    int bh=blockIdx.z, b=bh>>4, h=bh&15;
    int t0=blockIdx.x*32, d0=blockIdx.y*32;
    int lx=threadIdx.x&31, ly=threadIdx.x>>5;
    for(int i=0;i<32;i+=8){
        size_t src=(size_t)bh*VT_BH+(size_t)(d0+ly+i)*1024+t0+lx;
        tv[ly+i][lx]=gvT[src]; tg2[ly+i][lx]=gateT[src];
    }
    __syncthreads();
    for(int i=0;i<32;i+=8){
        int t=t0+ly+i;
        float v=tv[lx][ly+i], gg=tg2[lx][ly+i];
        size_t po=(size_t)(b*1024+t)*1024+h*64+d0+lx;
        __nv_bfloat16 hh=__float2bfloat16(v);
        g_gvHi[po]=hh; g_gvLo[po]=__float2bfloat16(v-__bfloat162float(hh));
        gate[((size_t)bh*1024+t)*64+d0+lx]=gg;
    }
}

// ---- fused splits ----
__global__ void splits_all_kernel(const float* __restrict__ x,
    const float* __restrict__ W0,const float* __restrict__ W1,const float* __restrict__ W2,
    const float* __restrict__ W3,const float* __restrict__ W4,const float* __restrict__ W5){
    int z=blockIdx.z;
    if(z==0){
        int i=blockIdx.x*256+threadIdx.x;
        for(; i<PLANE; i+=1024*256){
            float v=x[i]; __nv_bfloat16 h=__float2bfloat16(v);
            g_xHi[i]=h; g_xLo[i]=__float2bfloat16(v-__bfloat162float(h));
        }
        return;
    }
    const float* Ws[6]={W0,W1,W2,W3,W4,W5};
    int w=z-1;
    const float* W=Ws[w];
    __nv_bfloat16* hi=&g_WHi[w][0]; __nv_bfloat16* lo=&g_WLo[w][0];
    __shared__ float ts[32][33];
    int k0=(blockIdx.x>>5)*32, n0=(blockIdx.x&31)*32;
    int lx=threadIdx.x&31, ly=threadIdx.x>>5;
    for(int i=0;i<32;i+=8) ts[ly+i][lx]=W[(size_t)(k0+ly+i)*1024+n0+lx];
    __syncthreads();
    for(int i=0;i<32;i+=8){
        float v=ts[lx][ly+i];
        size_t dst=(size_t)(n0+ly+i)*1024+k0+lx;
        __nv_bfloat16 h=__float2bfloat16(v);
        hi[dst]=h; lo[dst]=__float2bfloat16(v-__bfloat162float(h));
    }
}

extern "C" void kernel_launch(void* const* d_in,const int* in_sizes,int n_in,
                              void* d_out,int out_size){
    const float* x=(const float*)d_in[0];
    const float* lam=(const float*)d_in[7];

    __nv_bfloat16 *xHi,*xLo,*DtHi,*DtLo,*gvHi,*gvLo;
    float *DtF,*VT,*gvT,*gateT,*gateS;
    cudaGetSymbolAddress((void**)&xHi,g_xHi);   cudaGetSymbolAddress((void**)&xLo,g_xLo);
    cudaGetSymbolAddress((void**)&DtF,g_DtF);   cudaGetSymbolAddress((void**)&DtHi,g_DtHi);
    cudaGetSymbolAddress((void**)&DtLo,g_DtLo);
    cudaGetSymbolAddress((void**)&VT,g_VT);     cudaGetSymbolAddress((void**)&gvT,g_gvT);
    cudaGetSymbolAddress((void**)&gateT,g_gateT);
    cudaGetSymbolAddress((void**)&gvHi,g_gvHi); cudaGetSymbolAddress((void**)&gvLo,g_gvLo);
    cudaGetSymbolAddress((void**)&gateS,g_gateS);

    const size_t DTSZ=(size_t)NBH*DT_BH;
    float* out=(float*)d_out;
    float* gate_dst=(out_size>=2*PLANE)? out+PLANE : gateS;

    cudaFuncSetAttribute(proj_all_kernel,      cudaFuncAttributeMaxDynamicSharedMemorySize,DSMEM);
    cudaFuncSetAttribute(prop_kernel,          cudaFuncAttributeMaxDynamicSharedMemorySize,DSMEM);
    cudaFuncSetAttribute(scores_softmax_kernel,cudaFuncAttributeMaxDynamicSharedMemorySize,SC_SMEM);

    // 1: all splits
    splits_all_kernel<<<dim3(1024,1,7),256>>>(x,(const float*)d_in[1],(const float*)d_in[2],
        (const float*)d_in[3],(const float*)d_in[4],(const float*)d_in[5],(const float*)d_in[6]);
    // 2: all 5 input projections
    proj_all_kernel<<<dim3(8,32,5),256,DSMEM>>>(xHi,xLo,0,nullptr);
    // 3: fused scores + softmax -> adjacency bf16
    scores_softmax_kernel<<<dim3(32,NBH),512,SC_SMEM>>>();
    // 4-6: propagation (launch 6 = prop #3 captured by ncu)
    dim3 ggrid(8,NBH), thr(256);
    prop_kernel<<<ggrid,thr,DSMEM>>>(DtHi,DtLo,nullptr,DtHi+DTSZ,DtLo+DTSZ,lam,1);
    prop_kernel<<<ggrid,thr,DSMEM>>>(DtHi+DTSZ,DtLo+DTSZ,nullptr,DtHi,DtLo,lam,1);
    prop_kernel<<<ggrid,thr,DSMEM>>>(DtHi,DtLo,DtF,nullptr,nullptr,lam,0);
    // 7: readout, 8: gather
    readout_kernel<<<dim3(8,NBH),256>>>(DtF,VT,gateT,gvT);
    gather_kernel<<<dim3(32,2,NBH),256>>>(gvT,gateT,gate_dst);
    // 9: output projection
    proj_all_kernel<<<dim3(8,32,1),256,DSMEM>>>(gvHi,gvLo,5,out);
}

// round 15
// speedup vs baseline: 1.0737x; 1.0737x over previous
#include <cuda_runtime.h>
#include <cuda_fp16.h>
#include <math.h>
#include <stdint.h>

constexpr int Bn=4, Tn=1024, DMn=1024, Hn=16, DKn=64;
constexpr int BT=Bn*Tn, PLANE=BT*DMn, NBH=Bn*Hn;
constexpr size_t SSZ=(size_t)NBH*Tn*Tn;
constexpr int DT_BH=128*Tn, VT_BH=64*Tn;
constexpr int PSZ=128*80;              // one 128x32 fp16 plane, 80B rows
constexpr int STG3=3*PSZ, STG4=4*PSZ;  // 2-prod / 3-prod stage sizes
constexpr int DSMEM=2*STG4;            // 81920 (covers both)
constexpr int DSMEM_PROP=2*STG3;       // 61440
// scores smem: Stile 32x1032 f32 (132096) + Q hi/lo (2x4608) + K 2 bufs x 1 plane x 128r x 144B
constexpr int SC_STILE=0, SC_Q=132096, SC_K=141312;
constexpr int QPL=4608, KPLC=18432;
constexpr int SC_SMEM=SC_K+2*KPLC;     // 178176

// ---- scratch (fp16 planes) ----
__device__ __half g_xHi[PLANE], g_xLo[PLANE];
__device__ __half g_WHi[6][DMn*DMn], g_WLo[6][DMn*DMn];   // W^T split [n][k]
__device__ __half g_QHi[PLANE], g_QLo[PLANE], g_K[PLANE]; // K single fp16
__device__ __half g_AHi[SSZ];                             // adjacency fp16
__device__ float  g_DtF[(size_t)NBH*DT_BH];
__device__ __half g_DtHi[2][(size_t)NBH*DT_BH], g_DtLo[2][(size_t)NBH*DT_BH];
__device__ float g_VT[(size_t)NBH*VT_BH], g_gvT[(size_t)NBH*VT_BH], g_gateT[(size_t)NBH*VT_BH];
__device__ __half g_gvHi[PLANE], g_gvLo[PLANE];
__device__ float g_gateS[(size_t)NBH*Tn*DKn];

// ---- helpers ----
__device__ __forceinline__ uint32_t smem_u32(const void* p){
    uint32_t a; asm("{ .reg .u64 t; cvta.to.shared.u64 t, %1; cvt.u32.u64 %0, t; }":"=r"(a):"l"(p)); return a;
}
__device__ __forceinline__ void cp16(uint32_t s, const void* g){
    asm volatile("cp.async.cg.shared.global [%0], [%1], 16;"::"r"(s),"l"(__cvta_generic_to_global(g)):"memory");
}
#define CP_COMMIT() asm volatile("cp.async.commit_group;":::"memory")
#define CP_WAIT0()  asm volatile("cp.async.wait_group 0;":::"memory")
#define LDM_X4(r,a) asm volatile("ldmatrix.sync.aligned.m8n8.x4.shared.b16 {%0,%1,%2,%3}, [%4];" \
    : "=r"((r)[0]),"=r"((r)[1]),"=r"((r)[2]),"=r"((r)[3]) : "r"(a))
__device__ __forceinline__ void mma16816(float* c, const uint32_t* a, uint32_t b0, uint32_t b1){
    asm volatile("mma.sync.aligned.m16n8k16.row.col.f32.f16.f16.f32 "
        "{%0,%1,%2,%3}, {%4,%5,%6,%7}, {%8,%9}, {%0,%1,%2,%3};"
        : "+f"(c[0]),"+f"(c[1]),"+f"(c[2]),"+f"(c[3])
        : "r"(a[0]),"r"(a[1]),"r"(a[2]),"r"(a[3]),"r"(b0),"r"(b1));
}
__device__ __forceinline__ void split16(float v, __half& h, __half& l){
    h=__float2half(v); l=__float2half(v-__half2float(h));
}

// ---- gemm128: 128x128 tile, 256 thr, 2-stage cp.async K=32, one barrier/chunk ----
// NPROD=3: Ah*Bh + Ah*Bl + Al*Bh (4 planes). NPROD=2: Ah*Bh + Al*Bh (3 planes).
__device__ __forceinline__ void load_plane(uint32_t s, const __half* g, int ld, int tid){
#pragma unroll
    for(int i=0;i<2;i++){
        int idx=tid+(i<<8), row=idx>>2, seg=idx&3;
        cp16(s+row*80+seg*16, g+(size_t)row*ld+seg*8);
    }
}
template<int NPROD>
__device__ __forceinline__ void load_chunk(uint32_t sb,
    const __half* aHi,const __half* aLo,int lda,
    const __half* bHi,const __half* bLo,int ldb,int c,int tid){
    size_t ko=(size_t)c*32;
    load_plane(sb,        aHi+ko, lda, tid);
    load_plane(sb+PSZ,    aLo+ko, lda, tid);
    load_plane(sb+2*PSZ,  bHi+ko, ldb, tid);
    if(NPROD==3) load_plane(sb+3*PSZ, bLo+ko, ldb, tid);
}
template<int NPROD>
__device__ __forceinline__ void compute_stage(uint32_t sb,int wm,int wn,int lane,float acc[2][8][4]){
#pragma unroll
    for(int kk=0;kk<32;kk+=16){
        uint32_t a_hi[2][4], a_lo[2][4];
#pragma unroll
        for(int mi=0;mi<2;mi++){
            uint32_t ad=sb+(uint32_t)((wm*32+mi*16+(lane&15))*80+(kk+((lane>>4)<<3))*2);
            LDM_X4(a_hi[mi],ad); LDM_X4(a_lo[mi],ad+PSZ);
        }
#pragma unroll
        for(int np=0;np<4;np++){
            uint32_t bd=sb+2*PSZ+(uint32_t)((wn*64+np*16+(lane&7)+((lane>>4)<<3))*80+(kk+((lane>>3)&1)*8)*2);
            uint32_t bh[4], bl[4];
            LDM_X4(bh,bd);
            if(NPROD==3){ LDM_X4(bl,bd+PSZ); }
#pragma unroll
            for(int mi=0;mi<2;mi++)
#pragma unroll
                for(int j=0;j<2;j++){
                    float* c=acc[mi][np*2+j];
                    mma16816(c,a_hi[mi],bh[2*j],bh[2*j+1]);
                    if(NPROD==3) mma16816(c,a_hi[mi],bl[2*j],bl[2*j+1]);
                    mma16816(c,a_lo[mi],bh[2*j],bh[2*j+1]);
                }
        }
    }
}
template<int NPROD>
__device__ __forceinline__ void gemm128(uint32_t dsm_u32,
    const __half* aHi,const __half* aLo,int lda,
    const __half* bHi,const __half* bLo,int ldb,
    int nchunks, float acc[2][8][4]){
    constexpr int STGZ = (NPROD==3)? STG4 : STG3;
    int tid=threadIdx.x, lane=tid&31, wid=tid>>5, wm=wid>>1, wn=wid&1;
    load_chunk<NPROD>(dsm_u32, aHi,aLo,lda, bHi,bLo,ldb, 0, tid); CP_COMMIT();
    for(int c=0;c<nchunks;c++){
        CP_WAIT0();
        __syncthreads();
        if(c+1<nchunks){
            load_chunk<NPROD>(dsm_u32+((c+1)&1)*STGZ, aHi,aLo,lda, bHi,bLo,ldb, c+1, tid);
            CP_COMMIT();
        }
        compute_stage<NPROD>(dsm_u32+(c&1)*STGZ, wm, wn, lane, acc);
    }
    __syncthreads();
}

// ---- fused projections: z selects weight + product count + output ----
__global__ void __launch_bounds__(256,2)
proj_all_kernel(const __half* __restrict__ aHi,const __half* __restrict__ aLo,
                int zbase, float* __restrict__ outF){
    extern __shared__ char dsm[];
    int z=blockIdx.z+zbase;
    const __half* wHi=&g_WHi[z][0];
    const __half* wLo=&g_WLo[z][0];
    float acc[2][8][4]={};
    int m0=blockIdx.y*128, n0=blockIdx.x*128;
    if(z<2)
        gemm128<2>(smem_u32(dsm), aHi+(size_t)m0*1024, aLo+(size_t)m0*1024,1024,
                   wHi+(size_t)n0*1024, nullptr,1024, 32, acc);
    else
        gemm128<3>(smem_u32(dsm), aHi+(size_t)m0*1024, aLo+(size_t)m0*1024,1024,
                   wHi+(size_t)n0*1024, wLo+(size_t)n0*1024,1024, 32, acc);
    int tid=threadIdx.x, lane=tid&31, wid=tid>>5, wm=wid>>1, wn=wid&1, g=lane>>2, tg=lane&3;
    int rowoff=(z==3)?64:0;
    if(z<2 || z==5){
#pragma unroll
        for(int mi=0;mi<2;mi++)
#pragma unroll
        for(int ni=0;ni<8;ni++){
            float* a4=acc[mi][ni];
            int cl=n0+wn*64+ni*8+tg*2;
#pragma unroll
            for(int p=0;p<2;p++){
                int row=m0+wm*32+mi*16+g+p*8;
                float v0=a4[2*p], v1=a4[2*p+1];
                size_t dst=(size_t)row*1024+cl;
                if(z==5){
                    *(float2*)&outF[dst]=make_float2(v0,v1);
                } else if(z==0){
                    __half h0,l0,h1,l1; split16(v0,h0,l0); split16(v1,h1,l1);
                    *(__half2*)&g_QHi[dst]=__halves2half2(h0,h1);
                    *(__half2*)&g_QLo[dst]=__halves2half2(l0,l1);
                } else {
                    *(__half2*)&g_K[dst]=__halves2half2(__float2half(v0),__float2half(v1));
                }
            }
        }
    } else {
        // transposed outputs staged through smem (coalesced along t)
        float* T=(float*)dsm;   // [128 cl][132]
#pragma unroll
        for(int mi=0;mi<2;mi++)
#pragma unroll
        for(int ni=0;ni<8;ni++){
            float* a4=acc[mi][ni];
            int cl=wn*64+ni*8+tg*2;
#pragma unroll
            for(int p=0;p<2;p++){
                int row=wm*32+mi*16+g+p*8;
                T[cl*132+row]    =a4[2*p];
                T[(cl+1)*132+row]=a4[2*p+1];
            }
        }
        __syncthreads();
        int j=tid>>1, half=tid&1;
        int dm=n0+j, h=dm>>6, d=dm&63, bq=m0>>10, bh=bq*16+h;
        int t0=(m0&1023)+half*64;
        const float* src=&T[j*132+half*64];
        if(z<4){
            size_t o0=(size_t)bh*DT_BH+(size_t)(rowoff+d)*1024+t0;
#pragma unroll
            for(int k8=0;k8<8;k8++){
                __align__(16) __half hb[8], lb[8];
#pragma unroll
                for(int k=0;k<8;k++) split16(src[k8*8+k], hb[k], lb[k]);
                *(uint4*)&g_DtHi[0][o0+k8*8]=*(const uint4*)hb;
                *(uint4*)&g_DtLo[0][o0+k8*8]=*(const uint4*)lb;
            }
        } else {
            size_t o0=(size_t)bh*VT_BH+(size_t)d*1024+t0;
#pragma unroll
            for(int k4=0;k4<16;k4++)
                *(float4*)&g_VT[o0+k4*4]=*(const float4*)&src[k4*4];
        }
    }
}

// ---- fused scores + softmax: 2 products (Qh*Kh + Ql*Kh), K single fp16 ----
__global__ void __launch_bounds__(512,1)
scores_softmax_kernel(){
    extern __shared__ char dsm[];
    float* Stile=(float*)(dsm+SC_STILE);           // [32][1032]
    uint32_t qoff=smem_u32(dsm)+SC_Q, kbase=smem_u32(dsm)+SC_K;
    int tid=threadIdx.x, lane=tid&31, wid=tid>>5;
    int wm=wid>>3, wn=wid&7;                       // 2m x 8n, warp tile 16x16
    int m0=blockIdx.x*32, bh=blockIdx.y, b=bh>>4, h=bh&15;
    size_t qg=(size_t)(b*1024+m0)*1024+h*64;
    size_t kg=(size_t)(b*1024)*1024+h*64;

    {   // Q hi+lo: 2 planes x 32 rows x 8 segs = 512 cp16
        int p=tid>>8, i=tid&255, row=i>>3, seg=i&7;
        const __half* src=(p? g_QLo:g_QHi)+qg+(size_t)row*1024+seg*8;
        cp16(qoff+p*QPL+row*144+seg*16, src);
    }
#pragma unroll
    for(int j=0;j<2;j++){   // K chunk 0: 128 rows x 8 segs = 1024 cp16
        int idx=tid+j*512, row=idx>>3, seg=idx&7;
        cp16(kbase+row*144+seg*16, g_K+kg+(size_t)row*1024+seg*8);
    }
    CP_COMMIT();

    for(int c=0;c<8;c++){
        CP_WAIT0();
        __syncthreads();
        if(c+1<8){
            uint32_t kb=kbase+((c+1)&1)*KPLC;
#pragma unroll
            for(int j=0;j<2;j++){
                int idx=tid+j*512, row=idx>>3, seg=idx&7;
                cp16(kb+row*144+seg*16, g_K+kg+(size_t)((c+1)*128+row)*1024+seg*8);
            }
            CP_COMMIT();
        }
        uint32_t kb=kbase+(c&1)*KPLC;
        float acc[2][4]={};
#pragma unroll
        for(int kk=0;kk<64;kk+=16){
            uint32_t ah[4], al[4];
            uint32_t ad=qoff+(uint32_t)((wm*16+(lane&15))*144+(kk+((lane>>4)<<3))*2);
            LDM_X4(ah,ad); LDM_X4(al,ad+QPL);
            uint32_t bd=kb+(uint32_t)((wn*16+(lane&7)+((lane>>4)<<3))*144+(kk+((lane>>3)&1)*8)*2);
            uint32_t bh4[4];
            LDM_X4(bh4,bd);
#pragma unroll
            for(int j=0;j<2;j++){
                float* cc=acc[j];
                mma16816(cc,ah,bh4[2*j],bh4[2*j+1]);
                mma16816(cc,al,bh4[2*j],bh4[2*j+1]);
            }
        }
        int cb=c*128+wn*16;
        int g=lane>>2, tg=lane&3;
#pragma unroll
        for(int j=0;j<2;j++)
#pragma unroll
            for(int p=0;p<2;p++){
                int r=wm*16+g+p*8, cc=cb+j*8+tg*2;
                Stile[r*1032+cc]  =acc[j][2*p]  *0.125f;
                Stile[r*1032+cc+1]=acc[j][2*p+1]*0.125f;
            }
    }
    __syncthreads();

    for(int rr=0;rr<2;rr++){
        int r=wid*2+rr;
        float* row=&Stile[r*1032];
        float mx=-1e30f;
        for(int c=lane;c<1024;c+=32) mx=fmaxf(mx,row[c]);
#pragma unroll
        for(int o=16;o;o>>=1) mx=fmaxf(mx,__shfl_xor_sync(0xffffffffu,mx,o));
        float s=0.f;
        for(int c=lane;c<1024;c+=32){ float e=expf(row[c]-mx); row[c]=e; s+=e; }
#pragma unroll
        for(int o=16;o;o>>=1) s+=__shfl_xor_sync(0xffffffffu,s,o);
        float inv=1.f/s;
        size_t ob=((size_t)bh<<20)+(size_t)(m0+r)*1024;
        for(int c=lane;c<1024;c+=32)
            g_AHi[ob+c]=__float2half(row[c]*inv);
    }
}

// ---- propagation: Dt_out=(1-lam)Dt_in + lam*(Dt_in@A^T); 2 products ----
__global__ void __launch_bounds__(256,2)
prop_kernel(const __half* __restrict__ dHi,const __half* __restrict__ dLo,
            float* __restrict__ outF,__half* __restrict__ outHi,__half* __restrict__ outLo,
            const float* __restrict__ lam_ptr, int ws){
    extern __shared__ char dsm[];
    float acc[2][8][4]={};
    int n0=blockIdx.x*128, bh=blockIdx.y;
    size_t ab=(size_t)bh*DT_BH, bb=((size_t)bh<<20)+(size_t)n0*1024;
    gemm128<2>(smem_u32(dsm), dHi+ab,dLo+ab,1024, g_AHi+bb,nullptr,1024, 32, acc);
    float lam=1.f/(1.f+expf(-lam_ptr[0])), oml=1.f-lam;
    int tid=threadIdx.x, lane=tid&31, wid=tid>>5, wm=wid>>1, wn=wid&1, g=lane>>2, tg=lane&3;
#pragma unroll
    for(int mi=0;mi<2;mi++)
#pragma unroll
    for(int ni=0;ni<8;ni++){
        float* a4=acc[mi][ni];
        int cl=n0+wn*64+ni*8+tg*2;
#pragma unroll
        for(int p=0;p<2;p++){
            int r=wm*32+mi*16+g+p*8;
            size_t off=ab+(size_t)r*1024+cl;
            __half2 h2=*(const __half2*)&dHi[off];
            __half2 l2=*(const __half2*)&dLo[off];
            float din0=__half2float(__low2half(h2))+__half2float(__low2half(l2));
            float din1=__half2float(__high2half(h2))+__half2float(__high2half(l2));
            float v0=oml*din0+lam*a4[2*p], v1=oml*din1+lam*a4[2*p+1];
            if(ws){
                __half h0,l0,h1,l1; split16(v0,h0,l0); split16(v1,h1,l1);
                *(__half2*)&outHi[off]=__halves2half2(h0,h1);
                *(__half2*)&outLo[off]=__halves2half2(l0,l1);
            } else {
                *(float2*)&outF[off]=make_float2(v0,v1);
            }
        }
    }
}

// ---- readout: one warp per (bh, d) column ----
__global__ void __launch_bounds__(256)
readout_kernel(const float* __restrict__ DtF,const float* __restrict__ VT,
               float* __restrict__ gateT,float* __restrict__ gvT){
    int bh=blockIdx.y, w=threadIdx.x>>5, lane=threadIdx.x&31;
    int d=blockIdx.x*8+w;
    const float* rRe=DtF+(size_t)bh*DT_BH+(size_t)d*1024;
    const float* rIm=DtF+(size_t)bh*DT_BH+(size_t)(64+d)*1024;
    const float* vb=VT+(size_t)bh*VT_BH;
    float sre=0.f,sim=0.f;
    for(int t=lane;t<1024;t+=32){ sre+=rRe[t]; sim+=rIm[t]; }
#pragma unroll
    for(int o=16;o;o>>=1){ sre+=__shfl_xor_sync(0xffffffffu,sre,o); sim+=__shfl_xor_sync(0xffffffffu,sim,o); }
    float mre=sre*(1.f/1024.f), mim=sim*(1.f/1024.f);
    float mn=sqrtf(mre*mre+mim*mim);
    float mx=-1e30f;
    for(int t=lane;t<1024;t+=32){
        float re=rRe[t], im=rIm[t];
        mx=fmaxf(mx,(re*mre+im*mim)/(sqrtf(re*re+im*im)*mn+1e-8f));
    }
#pragma unroll
    for(int o=16;o;o>>=1) mx=fmaxf(mx,__shfl_xor_sync(0xffffffffu,mx,o));
    float ss=0.f;
    for(int t=lane;t<1024;t+=32){
        float re=rRe[t], im=rIm[t];
        ss+=expf((re*mre+im*mim)/(sqrtf(re*re+im*im)*mn+1e-8f)-mx);
    }
#pragma unroll
    for(int o=16;o;o>>=1) ss+=__shfl_xor_sync(0xffffffffu,ss,o);
    float inv=1.f/ss;
    size_t ob=(size_t)bh*VT_BH+(size_t)d*1024;
    for(int t=lane;t<1024;t+=32){
        float re=rRe[t], im=rIm[t];
        float gt=expf((re*mre+im*mim)/(sqrtf(re*re+im*im)*mn+1e-8f)-mx)*inv;
        gateT[ob+t]=gt; gvT[ob+t]=gt*vb[(size_t)d*1024+t];
    }
}

// ---- gather ----
__global__ void gather_kernel(const float* __restrict__ gvT,const float* __restrict__ gateT,
                              float* __restrict__ gate){
    __shared__ float tv[32][33], tg2[32][33];
    int bh=blockIdx.z, b=bh>>4, h=bh&15;
    int t0=blockIdx.x*32, d0=blockIdx.y*32;
    int lx=threadIdx.x&31, ly=threadIdx.x>>5;
    for(int i=0;i<32;i+=8){
        size_t src=(size_t)bh*VT_BH+(size_t)(d0+ly+i)*1024+t0+lx;
        tv[ly+i][lx]=gvT[src]; tg2[ly+i][lx]=gateT[src];
    }
    __syncthreads();
    for(int i=0;i<32;i+=8){
        int t=t0+ly+i;
        float v=tv[lx][ly+i], gg=tg2[lx][ly+i];
        size_t po=(size_t)(b*1024+t)*1024+h*64+d0+lx;
        __half hh,ll; split16(v,hh,ll);
        g_gvHi[po]=hh; g_gvLo[po]=ll;
        gate[((size_t)bh*1024+t)*64+d0+lx]=gg;
    }
}

// ---- fused splits (fp16) ----
__global__ void splits_all_kernel(const float* __restrict__ x,
    const float* __restrict__ W0,const float* __restrict__ W1,const float* __restrict__ W2,
    const float* __restrict__ W3,const float* __restrict__ W4,const float* __restrict__ W5){
    int z=blockIdx.z;
    if(z==0){
        int i=blockIdx.x*256+threadIdx.x;
        for(; i<PLANE; i+=1024*256){
            __half h,l; split16(x[i],h,l);
            g_xHi[i]=h; g_xLo[i]=l;
        }
        return;
    }
    const float* Ws[6]={W0,W1,W2,W3,W4,W5};
    int w=z-1;
    const float* W=Ws[w];
    __half* hi=&g_WHi[w][0]; __half* lo=&g_WLo[w][0];
    __shared__ float ts[32][33];
    int k0=(blockIdx.x>>5)*32, n0=(blockIdx.x&31)*32;
    int lx=threadIdx.x&31, ly=threadIdx.x>>5;
    for(int i=0;i<32;i+=8) ts[ly+i][lx]=W[(size_t)(k0+ly+i)*1024+n0+lx];
    __syncthreads();
    for(int i=0;i<32;i+=8){
        size_t dst=(size_t)(n0+ly+i)*1024+k0+lx;
        __half h,l; split16(ts[lx][ly+i],h,l);
        hi[dst]=h; lo[dst]=l;
    }
}

extern "C" void kernel_launch(void* const* d_in,const int* in_sizes,int n_in,
                              void* d_out,int out_size){
    const float* x=(const float*)d_in[0];
    const float* lam=(const float*)d_in[7];

    __half *xHi,*xLo,*DtHi,*DtLo,*gvHi,*gvLo;
    float *DtF,*VT,*gvT,*gateT,*gateS;
    cudaGetSymbolAddress((void**)&xHi,g_xHi);   cudaGetSymbolAddress((void**)&xLo,g_xLo);
    cudaGetSymbolAddress((void**)&DtF,g_DtF);   cudaGetSymbolAddress((void**)&DtHi,g_DtHi);
    cudaGetSymbolAddress((void**)&DtLo,g_DtLo);
    cudaGetSymbolAddress((void**)&VT,g_VT);     cudaGetSymbolAddress((void**)&gvT,g_gvT);
    cudaGetSymbolAddress((void**)&gateT,g_gateT);
    cudaGetSymbolAddress((void**)&gvHi,g_gvHi); cudaGetSymbolAddress((void**)&gvLo,g_gvLo);
    cudaGetSymbolAddress((void**)&gateS,g_gateS);

    const size_t DTSZ=(size_t)NBH*DT_BH;
    float* out=(float*)d_out;
    float* gate_dst=(out_size>=2*PLANE)? out+PLANE : gateS;

    cudaFuncSetAttribute(proj_all_kernel,      cudaFuncAttributeMaxDynamicSharedMemorySize,DSMEM);
    cudaFuncSetAttribute(prop_kernel,          cudaFuncAttributeMaxDynamicSharedMemorySize,DSMEM_PROP);
    cudaFuncSetAttribute(scores_softmax_kernel,cudaFuncAttributeMaxDynamicSharedMemorySize,SC_SMEM);

    // 1: all splits
    splits_all_kernel<<<dim3(1024,1,7),256>>>(x,(const float*)d_in[1],(const float*)d_in[2],
        (const float*)d_in[3],(const float*)d_in[4],(const float*)d_in[5],(const float*)d_in[6]);
    // 2: all 5 input projections
    proj_all_kernel<<<dim3(8,32,5),256,DSMEM>>>(xHi,xLo,0,nullptr);
    // 3: fused scores + softmax -> adjacency fp16
    scores_softmax_kernel<<<dim3(32,NBH),512,SC_SMEM>>>();
    // 4-6: propagation (launch 6 = prop #3 captured by ncu)
    dim3 ggrid(8,NBH), thr(256);
    prop_kernel<<<ggrid,thr,DSMEM_PROP>>>(DtHi,DtLo,nullptr,DtHi+DTSZ,DtLo+DTSZ,lam,1);
    prop_kernel<<<ggrid,thr,DSMEM_PROP>>>(DtHi+DTSZ,DtLo+DTSZ,nullptr,DtHi,DtLo,lam,1);
    prop_kernel<<<ggrid,thr,DSMEM_PROP>>>(DtHi,DtLo,DtF,nullptr,nullptr,lam,0);
    // 7: readout, 8: gather
    readout_kernel<<<dim3(8,NBH),256>>>(DtF,VT,gateT,gvT);
    gather_kernel<<<dim3(32,2,NBH),256>>>(gvT,gateT,gate_dst);
    // 9: output projection
    proj_all_kernel<<<dim3(8,32,1),256,DSMEM>>>(gvHi,gvLo,5,out);
}